// round 13
// baseline (speedup 1.0000x reference)
#include <cuda_runtime.h>
#include <cuda_bf16.h>
#include <cstdint>

#define SEQ 2048
#define HID 1024
#define NH  16
#define HD  64
#define VOCABN 50259

// split-bf16: logical K' = 3*1024, physical storage K = 2048 ([hi|lo])
#define KSTOR 2048
#define KSB  (KSTOR * 2)   // bytes per stored row = 4096
#define BM 256
#define BN 128
#define BK 32              // bf16 elems per K chunk (64 bytes)
#define NCH 96             // 3 slots x 32 chunks
#define STAGES 4
#define ROWB 80            // padded smem row: 32 bf16 + 8 pad = 80 bytes
#define A_BYTES (BM * ROWB)             // 20480
#define B_BYTES (BN * ROWB)             // 10240
#define STAGE_BYTES (A_BYTES + B_BYTES) // 30720
#define SMEM_BYTES (STAGES * STAGE_BYTES) // 122880

// ---- scratch (device globals; no allocation allowed) ----
__device__ float g_x[SEQ * HID];
__device__ float g_xpe[SEQ * HID];
__device__ float g_qkv[SEQ * 3 * HID];
__device__ float g_attn[SEQ * HID];
__device__ __align__(16) __nv_bfloat16 g_tok[(size_t)VOCABN * KSTOR];  // 206 MB
__device__ __align__(16) __nv_bfloat16 g_w[(size_t)3 * HID * KSTOR];
__device__ __align__(16) __nv_bfloat16 g_ap[(size_t)SEQ * KSTOR];
__device__ __align__(16) __nv_bfloat16 g_ax[(size_t)SEQ * KSTOR];
__device__ __align__(16) __nv_bfloat16 g_aat[(size_t)SEQ * KSTOR];

// ============================================================
// helpers
// ============================================================
__device__ __forceinline__ uint32_t smem_to_u32(const void* p) {
    uint32_t a;
    asm("{ .reg .u64 t; cvta.to.shared.u64 t, %1; cvt.u32.u64 %0, t; }" : "=r"(a) : "l"(p));
    return a;
}
__device__ __forceinline__ void cp16(uint32_t dst, const void* src) {
    asm volatile("cp.async.cg.shared.global [%0], [%1], 16;" :: "r"(dst), "l"(src));
}
#define CP_COMMIT() asm volatile("cp.async.commit_group;" ::: "memory")
#define CP_WAIT2()  asm volatile("cp.async.wait_group %0;" :: "n"(STAGES - 2) : "memory")

__device__ __forceinline__ void ldsm4(uint32_t* r, uint32_t addr) {
    asm volatile("ldmatrix.sync.aligned.m8n8.x4.shared.b16 {%0,%1,%2,%3}, [%4];"
                 : "=r"(r[0]), "=r"(r[1]), "=r"(r[2]), "=r"(r[3]) : "r"(addr));
}
__device__ __forceinline__ void mma16816(float* c, const uint32_t* a, const uint32_t* b) {
    asm volatile(
        "mma.sync.aligned.m16n8k16.row.col.f32.bf16.bf16.f32 "
        "{%0,%1,%2,%3}, {%4,%5,%6,%7}, {%8,%9}, {%0,%1,%2,%3};"
        : "+f"(c[0]), "+f"(c[1]), "+f"(c[2]), "+f"(c[3])
        : "r"(a[0]), "r"(a[1]), "r"(a[2]), "r"(a[3]), "r"(b[0]), "r"(b[1]));
}

// ============================================================
// Embedding: x = tok_emb[ids], xpe = x + pos_emb
// ============================================================
__global__ __launch_bounds__(256) void embed_kernel(
    const int* __restrict__ ids, const float* __restrict__ tok,
    const float* __restrict__ pos)
{
    int i = blockIdx.x * 256 + threadIdx.x;
    int s = i >> 8;
    int c = i & 255;
    int t = ids[s];
    float4 v = reinterpret_cast<const float4*>(tok + (size_t)t * HID)[c];
    float4 p = reinterpret_cast<const float4*>(pos + (size_t)s * HID)[c];
    reinterpret_cast<float4*>(g_x + (size_t)s * HID)[c] = v;
    float4 w = make_float4(v.x + p.x, v.y + p.y, v.z + p.z, v.w + p.w);
    reinterpret_cast<float4*>(g_xpe + (size_t)s * HID)[c] = w;
}

// ============================================================
// Split conversion: fp32 [R,1024] -> bf16 [R,2048] = [hi | lo]
// The GEMM's chunk remap realizes AhBh + AlBh + AhBl (err ~ AlBl ~ 4e-6).
// ============================================================
__global__ __launch_bounds__(256) void conv_split(
    const float* __restrict__ src, __nv_bfloat16* __restrict__ dst, int total4)
{
    int i = blockIdx.x * 256 + threadIdx.x;
    if (i >= total4) return;
    int r = i >> 8;
    int k4 = (i & 255) * 4;
    float4 v = reinterpret_cast<const float4*>(src)[i];
    float vv[4] = {v.x, v.y, v.z, v.w};
    __nv_bfloat16 h[4], l[4];
#pragma unroll
    for (int j = 0; j < 4; j++) {
        h[j] = __float2bfloat16(vv[j]);
        l[j] = __float2bfloat16(vv[j] - __bfloat162float(h[j]));
    }
    __nv_bfloat162 hp0, hp1, lp0, lp1;
    hp0.x = h[0]; hp0.y = h[1]; hp1.x = h[2]; hp1.y = h[3];
    lp0.x = l[0]; lp0.y = l[1]; lp1.x = l[2]; lp1.y = l[3];
    __nv_bfloat16* row = dst + (size_t)r * KSTOR;
    __nv_bfloat162* ph = reinterpret_cast<__nv_bfloat162*>(row + k4);
    ph[0] = hp0; ph[1] = hp1;
    __nv_bfloat162* pl = reinterpret_cast<__nv_bfloat162*>(row + 1024 + k4);
    pl[0] = lp0; pl[1] = lp1;
}

// ============================================================
// mma.sync bf16 GEMM with slot-remapped K loop (logical K' = 3072):
//   slot 0 (ch  0..31): Ah x Bh     slot 1 (ch 32..63): Al x Bh
//   slot 2 (ch 64..95): Ah x Bl
// Tile 256x128x32, 8 warps (warp tile 64x64, 4Mx2N), 4-stage cp.async.
// MODE 0: C = acc        MODE 1: C = resid + acc; xpe_out = C + pe
// ============================================================
__device__ __forceinline__ void load_chunk(
    uint32_t sA, uint32_t sB,
    const __nv_bfloat16* __restrict__ Ag, const __nv_bfloat16* __restrict__ Bg,
    int rowBase, int colBase, int Nb, int ch, int tid)
{
    int slot = ch >> 5, c = ch & 31;
    int aCh = (slot == 1) ? c + 32 : c;     // Al lives in cols 1024..2047
    int bCh = (slot == 2) ? c + 32 : c;     // Bl lives in cols 1024..2047

    const char* abase = (const char*)Ag + (size_t)aCh * 64;
#pragma unroll
    for (int it = 0; it < 4; it++) {
        int q = tid + it * 256;          // 0..1023
        int r = q >> 2, cc = q & 3;
        cp16(sA + r * ROWB + cc * 16,
             abase + (size_t)(rowBase + r) * KSB + cc * 16);
    }
    const char* bbase = (const char*)Bg + (size_t)bCh * 64;
#pragma unroll
    for (int it = 0; it < 2; it++) {
        int q = tid + it * 256;          // 0..511
        int r = q >> 2, cc = q & 3;
        int br = colBase + r;
        if (br > Nb - 1) br = Nb - 1;    // clamp; duplicated rows never stored
        cp16(sB + r * ROWB + cc * 16,
             bbase + (size_t)br * KSB + cc * 16);
    }
}

template <int MODE>
__global__ __launch_bounds__(256, 1) void mm_kernel(
    const __nv_bfloat16* __restrict__ Ag, const __nv_bfloat16* __restrict__ Bg,
    float* __restrict__ C, int Nb, int ldc,
    const float* __restrict__ resid, const float* __restrict__ pe,
    float* __restrict__ xpe_out)
{
    extern __shared__ __align__(128) char smem[];
    uint32_t sbase = smem_to_u32(smem);
    const int tid  = threadIdx.x;
    const int wid  = tid >> 5;
    const int lane = tid & 31;
    const int rowBase = blockIdx.y * BM;
    const int colBase = blockIdx.x * BN;
    const int wm = (wid & 3) * 64;    // warp M offset (4 warps over 256 rows)
    const int wn = (wid >> 2) * 64;   // warp N offset (2 warps over 128 cols)

    float acc[4][8][4];
#pragma unroll
    for (int mi = 0; mi < 4; mi++)
#pragma unroll
        for (int ni = 0; ni < 8; ni++)
#pragma unroll
            for (int e = 0; e < 4; e++) acc[mi][ni][e] = 0.0f;

    // prologue: stages 0..2
#pragma unroll
    for (int j = 0; j < STAGES - 1; j++) {
        uint32_t sA = sbase + j * STAGE_BYTES;
        load_chunk(sA, sA + A_BYTES, Ag, Bg, rowBase, colBase, Nb, j, tid);
        CP_COMMIT();
    }

    // ldmatrix lane offsets
    const int aRow = lane & 15;
    const int aCol = (lane >> 4) * 16;
    const int bRow = (lane & 7) + ((lane >> 4) << 3);
    const int bCol = ((lane >> 3) & 1) * 16;

    for (int j = 0; j < NCH; j++) {
        CP_WAIT2();
        __syncthreads();
        if (j + STAGES - 1 < NCH) {
            uint32_t sA2 = sbase + ((j + STAGES - 1) % STAGES) * STAGE_BYTES;
            load_chunk(sA2, sA2 + A_BYTES, Ag, Bg, rowBase, colBase, Nb,
                       j + STAGES - 1, tid);
        }
        CP_COMMIT();

        uint32_t sA = sbase + (j % STAGES) * STAGE_BYTES;
        uint32_t sB = sA + A_BYTES;
#pragma unroll
        for (int ks = 0; ks < 2; ks++) {
            uint32_t a[4][4];
#pragma unroll
            for (int mi = 0; mi < 4; mi++)
                ldsm4(a[mi], sA + (wm + mi * 16 + aRow) * ROWB + ks * 32 + aCol);
            uint32_t b[8][2];
#pragma unroll
            for (int nj = 0; nj < 4; nj++) {
                uint32_t r[4];
                ldsm4(r, sB + (wn + nj * 16 + bRow) * ROWB + ks * 32 + bCol);
                b[nj * 2 + 0][0] = r[0]; b[nj * 2 + 0][1] = r[1];
                b[nj * 2 + 1][0] = r[2]; b[nj * 2 + 1][1] = r[3];
            }
#pragma unroll
            for (int mi = 0; mi < 4; mi++)
#pragma unroll
                for (int ni = 0; ni < 8; ni++)
                    mma16816(acc[mi][ni], a[mi], b[ni]);
        }
    }

    // epilogue (scalar stores only — ldc may be odd for the LM head)
    const int erow = lane >> 2;
    const int ecol = (lane & 3) * 2;
#pragma unroll
    for (int mi = 0; mi < 4; mi++) {
#pragma unroll
        for (int half = 0; half < 2; half++) {
            int gr = rowBase + wm + mi * 16 + erow + half * 8;
            float* crow = C + (size_t)gr * ldc;
#pragma unroll
            for (int ni = 0; ni < 8; ni++) {
                int gc = colBase + wn + ni * 8 + ecol;
                float v0 = acc[mi][ni][half * 2 + 0];
                float v1 = acc[mi][ni][half * 2 + 1];
                if (MODE == 0) {
                    if (gc < Nb)     crow[gc]     = v0;
                    if (gc + 1 < Nb) crow[gc + 1] = v1;
                } else {
                    const float* rr = resid + (size_t)gr * HID;
                    const float* pp = pe + (size_t)gr * HID;
                    float* xx = xpe_out + (size_t)gr * HID;
                    float w0 = rr[gc] + v0;
                    float w1 = rr[gc + 1] + v1;
                    crow[gc] = w0; crow[gc + 1] = w1;
                    xx[gc] = w0 + pp[gc]; xx[gc + 1] = w1 + pp[gc + 1];
                }
            }
        }
    }
}

// ============================================================
// Flash attention (fp32), causal, hd=64.
// Q prescaled by 0.125*log2(e); probabilities via exp2f (1 MUFU each).
// ============================================================
#define QSCALE (0.125f * 1.44269504088896f)

__global__ __launch_bounds__(256) void attn_kernel(
    const float* __restrict__ qkv, float* __restrict__ out)
{
    __shared__ __align__(16) float Qts[HD][64];
    __shared__ __align__(16) float KP[64][64];
    __shared__ __align__(16) float Vs[64][64];

    int tid = threadIdx.x;
    int tx = tid & 15, ty = tid >> 4;
    int qt = blockIdx.x;
    int h  = blockIdx.y;

#pragma unroll
    for (int it = 0; it < 4; it++) {
        int li = tid + it * 256;
        int r  = li >> 4;
        int c4 = (li & 15) * 4;
        float4 v = *reinterpret_cast<const float4*>(
            qkv + (size_t)(qt * 64 + r) * (3 * HID) + h * HD + c4);
        Qts[c4 + 0][r] = v.x * QSCALE; Qts[c4 + 1][r] = v.y * QSCALE;
        Qts[c4 + 2][r] = v.z * QSCALE; Qts[c4 + 3][r] = v.w * QSCALE;
    }

    float m_i[4], l_i[4], o[4][4];
#pragma unroll
    for (int i = 0; i < 4; i++) {
        m_i[i] = -1e30f; l_i[i] = 0.0f;
#pragma unroll
        for (int j = 0; j < 4; j++) o[i][j] = 0.0f;
    }

    for (int kt = 0; kt <= qt; kt++) {
        __syncthreads();
#pragma unroll
        for (int it = 0; it < 4; it++) {
            int li = tid + it * 256;
            int r  = li >> 4;
            int c4 = (li & 15) * 4;
            const float* rowp = qkv + (size_t)(kt * 64 + r) * (3 * HID) + h * HD + c4;
            float4 kv = *reinterpret_cast<const float4*>(rowp + HID);
            KP[c4 + 0][r] = kv.x; KP[c4 + 1][r] = kv.y;
            KP[c4 + 2][r] = kv.z; KP[c4 + 3][r] = kv.w;
            float4 vv = *reinterpret_cast<const float4*>(rowp + 2 * HID);
            *reinterpret_cast<float4*>(&Vs[r][c4]) = vv;
        }
        __syncthreads();

        float s[4][4];
#pragma unroll
        for (int i = 0; i < 4; i++)
#pragma unroll
            for (int j = 0; j < 4; j++) s[i][j] = 0.0f;
#pragma unroll
        for (int kk = 0; kk < HD; kk++) {
            float4 a = *reinterpret_cast<const float4*>(&Qts[kk][ty * 4]);
            float4 b = *reinterpret_cast<const float4*>(&KP[kk][tx * 4]);
            float av[4] = {a.x, a.y, a.z, a.w};
            float bv[4] = {b.x, b.y, b.z, b.w};
#pragma unroll
            for (int i = 0; i < 4; i++)
#pragma unroll
                for (int j = 0; j < 4; j++)
                    s[i][j] = fmaf(av[i], bv[j], s[i][j]);
        }

#pragma unroll
        for (int i = 0; i < 4; i++)
#pragma unroll
            for (int j = 0; j < 4; j++) {
                if (kt == qt && (ty * 4 + i) < (tx * 4 + j)) s[i][j] = -1e30f;
            }

        float p[4][4];
#pragma unroll
        for (int i = 0; i < 4; i++) {
            float rm = fmaxf(fmaxf(s[i][0], s[i][1]), fmaxf(s[i][2], s[i][3]));
            rm = fmaxf(rm, __shfl_xor_sync(0xffffffffu, rm, 1));
            rm = fmaxf(rm, __shfl_xor_sync(0xffffffffu, rm, 2));
            rm = fmaxf(rm, __shfl_xor_sync(0xffffffffu, rm, 4));
            rm = fmaxf(rm, __shfl_xor_sync(0xffffffffu, rm, 8));
            float mn = fmaxf(m_i[i], rm);
            float alpha = exp2f(m_i[i] - mn);
            float rs = 0.0f;
#pragma unroll
            for (int j = 0; j < 4; j++) { p[i][j] = exp2f(s[i][j] - mn); rs += p[i][j]; }
            rs += __shfl_xor_sync(0xffffffffu, rs, 1);
            rs += __shfl_xor_sync(0xffffffffu, rs, 2);
            rs += __shfl_xor_sync(0xffffffffu, rs, 4);
            rs += __shfl_xor_sync(0xffffffffu, rs, 8);
            l_i[i] = l_i[i] * alpha + rs;
            m_i[i] = mn;
#pragma unroll
            for (int j = 0; j < 4; j++) o[i][j] *= alpha;
        }

        __syncthreads();
#pragma unroll
        for (int i = 0; i < 4; i++)
#pragma unroll
            for (int j = 0; j < 4; j++) KP[ty * 4 + i][tx * 4 + j] = p[i][j];
        __syncthreads();

#pragma unroll
        for (int kk = 0; kk < 64; kk++) {
            float a0 = KP[ty * 4 + 0][kk];
            float a1 = KP[ty * 4 + 1][kk];
            float a2 = KP[ty * 4 + 2][kk];
            float a3 = KP[ty * 4 + 3][kk];
            float4 b = *reinterpret_cast<const float4*>(&Vs[kk][tx * 4]);
            float bv[4] = {b.x, b.y, b.z, b.w};
#pragma unroll
            for (int j = 0; j < 4; j++) {
                o[0][j] = fmaf(a0, bv[j], o[0][j]);
                o[1][j] = fmaf(a1, bv[j], o[1][j]);
                o[2][j] = fmaf(a2, bv[j], o[2][j]);
                o[3][j] = fmaf(a3, bv[j], o[3][j]);
            }
        }
    }

#pragma unroll
    for (int i = 0; i < 4; i++) {
        float inv = 1.0f / l_i[i];
        int gq = qt * 64 + ty * 4 + i;
#pragma unroll
        for (int j = 0; j < 4; j++)
            out[(size_t)gq * HID + h * HD + tx * 4 + j] = o[i][j] * inv;
    }
}

// ============================================================
// launch
// ============================================================
extern "C" void kernel_launch(void* const* d_in, const int* in_sizes, int n_in,
                              void* d_out, int out_size)
{
    const int*   ids   = (const int*)d_in[0];
    const float* tok   = (const float*)d_in[1];
    const float* pos   = (const float*)d_in[2];
    const float* Wqkv0 = (const float*)d_in[3];
    const float* Wo0   = (const float*)d_in[4];
    const float* Wqkv1 = (const float*)d_in[5];
    const float* Wo1   = (const float*)d_in[6];
    float* out = (float*)d_out;

    float *x, *xpe, *qkvb, *attnb;
    __nv_bfloat16 *tokb, *wb, *apb, *axb, *aatb;
    cudaGetSymbolAddress((void**)&x,     g_x);
    cudaGetSymbolAddress((void**)&xpe,   g_xpe);
    cudaGetSymbolAddress((void**)&qkvb,  g_qkv);
    cudaGetSymbolAddress((void**)&attnb, g_attn);
    cudaGetSymbolAddress((void**)&tokb,  g_tok);
    cudaGetSymbolAddress((void**)&wb,    g_w);
    cudaGetSymbolAddress((void**)&apb,   g_ap);
    cudaGetSymbolAddress((void**)&axb,   g_ax);
    cudaGetSymbolAddress((void**)&aatb,  g_aat);

    cudaFuncSetAttribute(mm_kernel<0>, cudaFuncAttributeMaxDynamicSharedMemorySize, SMEM_BYTES);
    cudaFuncSetAttribute(mm_kernel<1>, cudaFuncAttributeMaxDynamicSharedMemorySize, SMEM_BYTES);

    dim3 blk(256);
    const int SEQ4 = SEQ * 256;
    const int VOC4 = VOCABN * 256;

    // tok_emb split (for LM head)
    conv_split<<<(VOC4 + 255) / 256, blk>>>(tok, tokb, VOC4);

    // embed
    embed_kernel<<<SEQ * HID / 4 / 256, blk>>>(ids, tok, pos);
    conv_split<<<SEQ4 / 256, blk>>>(xpe, apb, SEQ4);
    conv_split<<<SEQ4 / 256, blk>>>(x,   axb, SEQ4);

    dim3 grid_qk(2048 / BN, SEQ / BM);                  // (16, 8)
    dim3 grid_h (1024 / BN, SEQ / BM);                  // (8, 8)
    dim3 grid_lm((VOCABN + BN - 1) / BN, SEQ / BM);     // (393, 8)
    dim3 grid_at(SEQ / 64, NH);

    const float* Wq[2] = {Wqkv0, Wqkv1};
    const float* Wo[2] = {Wo0, Wo1};
    for (int l = 0; l < 2; l++) {
        conv_split<<<(3072 * 256) / 256, blk>>>(Wq[l], wb, 3072 * 256);
        // qk projection: A = xpe', B = Wqkv'[0:2048]
        mm_kernel<0><<<grid_qk, blk, SMEM_BYTES>>>(apb, wb, qkvb, 2048, 3 * HID,
                                                   nullptr, nullptr, nullptr);
        // v projection: A = x', B = Wqkv'[2048:3072]
        mm_kernel<0><<<grid_h, blk, SMEM_BYTES>>>(axb, wb + (size_t)2048 * KSTOR,
                                                  qkvb + 2048, 1024, 3 * HID,
                                                  nullptr, nullptr, nullptr);
        attn_kernel<<<grid_at, blk>>>(qkvb, attnb);
        conv_split<<<SEQ4 / 256, blk>>>(attnb, aatb, SEQ4);
        conv_split<<<(1024 * 256) / 256, blk>>>(Wo[l], wb, 1024 * 256);
        // out proj + residual + pos-emb fusion
        mm_kernel<1><<<grid_h, blk, SMEM_BYTES>>>(aatb, wb, x, 1024, HID, x, pos, xpe);
        conv_split<<<SEQ4 / 256, blk>>>(xpe, apb, SEQ4);
        conv_split<<<SEQ4 / 256, blk>>>(x,   axb, SEQ4);
    }

    // LM head: A = x', B = tok'
    mm_kernel<0><<<grid_lm, blk, SMEM_BYTES>>>(axb, tokb, out, VOCABN, VOCABN,
                                               nullptr, nullptr, nullptr);
}

// round 14
// speedup vs baseline: 1.6007x; 1.6007x over previous
#include <cuda_runtime.h>
#include <cuda_bf16.h>
#include <cuda_fp16.h>
#include <cstdint>

#define SEQ 2048
#define HID 1024
#define NH  16
#define HD  64
#define VOCABN 50259

// split-bf16 storage: [hi | lo], K stored = 2048 (layer GEMMs)
#define KSTOR 2048
#define BM 256
#define BN 128
#define BK 32              // bf16/fp16 elems per K chunk (64 bytes)
#define STAGES 4
#define ROWB 80            // padded smem row: 32 elems + 8 pad = 80 bytes
#define A_BYTES (BM * ROWB)             // 20480
#define B_BYTES (BN * ROWB)             // 10240
#define STAGE_BYTES (A_BYTES + B_BYTES) // 30720
#define SMEM_BYTES (STAGES * STAGE_BYTES) // 122880

// ---- scratch (device globals; no allocation allowed) ----
__device__ float g_x[SEQ * HID];
__device__ float g_xpe[SEQ * HID];
__device__ float g_qkv[SEQ * 3 * HID];
__device__ float g_attn[SEQ * HID];
__device__ __align__(16) __half        g_tokh[(size_t)VOCABN * HID];   // 103 MB fp16
__device__ __align__(16) __half        g_axh[(size_t)SEQ * HID];       // x fp16 (LM head A)
__device__ __align__(16) __nv_bfloat16 g_w[(size_t)3 * HID * KSTOR];
__device__ __align__(16) __nv_bfloat16 g_ap[(size_t)SEQ * KSTOR];
__device__ __align__(16) __nv_bfloat16 g_ax[(size_t)SEQ * KSTOR];
__device__ __align__(16) __nv_bfloat16 g_aat[(size_t)SEQ * KSTOR];

// ============================================================
// helpers
// ============================================================
__device__ __forceinline__ uint32_t smem_to_u32(const void* p) {
    uint32_t a;
    asm("{ .reg .u64 t; cvta.to.shared.u64 t, %1; cvt.u32.u64 %0, t; }" : "=r"(a) : "l"(p));
    return a;
}
__device__ __forceinline__ void cp16(uint32_t dst, const void* src) {
    asm volatile("cp.async.cg.shared.global [%0], [%1], 16;" :: "r"(dst), "l"(src));
}
#define CP_COMMIT() asm volatile("cp.async.commit_group;" ::: "memory")
#define CP_WAIT2()  asm volatile("cp.async.wait_group %0;" :: "n"(STAGES - 2) : "memory")

__device__ __forceinline__ void ldsm4(uint32_t* r, uint32_t addr) {
    asm volatile("ldmatrix.sync.aligned.m8n8.x4.shared.b16 {%0,%1,%2,%3}, [%4];"
                 : "=r"(r[0]), "=r"(r[1]), "=r"(r[2]), "=r"(r[3]) : "r"(addr));
}
__device__ __forceinline__ void mma_bf16(float* c, const uint32_t* a, const uint32_t* b) {
    asm volatile(
        "mma.sync.aligned.m16n8k16.row.col.f32.bf16.bf16.f32 "
        "{%0,%1,%2,%3}, {%4,%5,%6,%7}, {%8,%9}, {%0,%1,%2,%3};"
        : "+f"(c[0]), "+f"(c[1]), "+f"(c[2]), "+f"(c[3])
        : "r"(a[0]), "r"(a[1]), "r"(a[2]), "r"(a[3]), "r"(b[0]), "r"(b[1]));
}
__device__ __forceinline__ void mma_fp16(float* c, const uint32_t* a, const uint32_t* b) {
    asm volatile(
        "mma.sync.aligned.m16n8k16.row.col.f32.f16.f16.f32 "
        "{%0,%1,%2,%3}, {%4,%5,%6,%7}, {%8,%9}, {%0,%1,%2,%3};"
        : "+f"(c[0]), "+f"(c[1]), "+f"(c[2]), "+f"(c[3])
        : "r"(a[0]), "r"(a[1]), "r"(a[2]), "r"(a[3]), "r"(b[0]), "r"(b[1]));
}

// ============================================================
// Embedding: x = tok_emb[ids], xpe = x + pos_emb
// ============================================================
__global__ __launch_bounds__(256) void embed_kernel(
    const int* __restrict__ ids, const float* __restrict__ tok,
    const float* __restrict__ pos)
{
    int i = blockIdx.x * 256 + threadIdx.x;
    int s = i >> 8;
    int c = i & 255;
    int t = ids[s];
    float4 v = reinterpret_cast<const float4*>(tok + (size_t)t * HID)[c];
    float4 p = reinterpret_cast<const float4*>(pos + (size_t)s * HID)[c];
    reinterpret_cast<float4*>(g_x + (size_t)s * HID)[c] = v;
    float4 w = make_float4(v.x + p.x, v.y + p.y, v.z + p.z, v.w + p.w);
    reinterpret_cast<float4*>(g_xpe + (size_t)s * HID)[c] = w;
}

// ============================================================
// Split conversion: fp32 [R,1024] -> bf16 [R,2048] = [hi | lo]
// ============================================================
__global__ __launch_bounds__(256) void conv_split(
    const float* __restrict__ src, __nv_bfloat16* __restrict__ dst, int total4)
{
    int i = blockIdx.x * 256 + threadIdx.x;
    if (i >= total4) return;
    int r = i >> 8;
    int k4 = (i & 255) * 4;
    float4 v = reinterpret_cast<const float4*>(src)[i];
    float vv[4] = {v.x, v.y, v.z, v.w};
    __nv_bfloat16 h[4], l[4];
#pragma unroll
    for (int j = 0; j < 4; j++) {
        h[j] = __float2bfloat16(vv[j]);
        l[j] = __float2bfloat16(vv[j] - __bfloat162float(h[j]));
    }
    __nv_bfloat162 hp0, hp1, lp0, lp1;
    hp0.x = h[0]; hp0.y = h[1]; hp1.x = h[2]; hp1.y = h[3];
    lp0.x = l[0]; lp0.y = l[1]; lp1.x = l[2]; lp1.y = l[3];
    __nv_bfloat16* row = dst + (size_t)r * KSTOR;
    __nv_bfloat162* ph = reinterpret_cast<__nv_bfloat162*>(row + k4);
    ph[0] = hp0; ph[1] = hp1;
    __nv_bfloat162* pl = reinterpret_cast<__nv_bfloat162*>(row + 1024 + k4);
    pl[0] = lp0; pl[1] = lp1;
}

// ============================================================
// fp16 conversion: fp32 [R,1024] -> fp16 [R,1024]
// ============================================================
__global__ __launch_bounds__(256) void conv_half(
    const float* __restrict__ src, __half* __restrict__ dst, int total4)
{
    int i = blockIdx.x * 256 + threadIdx.x;
    if (i >= total4) return;
    float4 v = reinterpret_cast<const float4*>(src)[i];
    __half2 h0 = __floats2half2_rn(v.x, v.y);
    __half2 h1 = __floats2half2_rn(v.z, v.w);
    reinterpret_cast<__half2*>(dst)[i * 2 + 0] = h0;
    reinterpret_cast<__half2*>(dst)[i * 2 + 1] = h1;
}

// ============================================================
// mma.sync GEMM, tile 256x128x32, 8 warps (4Mx2N, warp tile 64x64).
// SPLIT3=1 (bf16): 96 logical chunks over [hi|lo] storage (K row = 4096 B):
//     slot0 AhBh, slot1 AlBh, slot2 AhBl
// SPLIT3=0 (fp16): 32 chunks, K row = 2048 B, single pass.
// MODE 0: C = acc        MODE 1: C = resid + acc; xpe_out = C + pe
// ============================================================
template <int SPLIT3>
__device__ __forceinline__ void load_chunk(
    uint32_t sA, uint32_t sB, const char* Ag, const char* Bg,
    int rowBase, int colBase, int Nb, int ch, int tid)
{
    constexpr int KSB = SPLIT3 ? 4096 : 2048;   // bytes per stored row
    int aCh, bCh;
    if (SPLIT3) {
        int slot = ch >> 5, c = ch & 31;
        aCh = (slot == 1) ? c + 32 : c;     // Al in cols 1024..2047
        bCh = (slot == 2) ? c + 32 : c;     // Bl in cols 1024..2047
    } else {
        aCh = ch; bCh = ch;
    }

    const char* abase = Ag + (size_t)aCh * 64;
#pragma unroll
    for (int it = 0; it < 4; it++) {
        int q = tid + it * 256;          // 0..1023
        int r = q >> 2, cc = q & 3;
        cp16(sA + r * ROWB + cc * 16,
             abase + (size_t)(rowBase + r) * KSB + cc * 16);
    }
    const char* bbase = Bg + (size_t)bCh * 64;
#pragma unroll
    for (int it = 0; it < 2; it++) {
        int q = tid + it * 256;          // 0..511
        int r = q >> 2, cc = q & 3;
        int br = colBase + r;
        if (br > Nb - 1) br = Nb - 1;    // clamp; duplicated rows never stored
        cp16(sB + r * ROWB + cc * 16,
             bbase + (size_t)br * KSB + cc * 16);
    }
}

template <int MODE, int SPLIT3>
__global__ __launch_bounds__(256, 1) void mm_kernel(
    const void* __restrict__ Agv, const void* __restrict__ Bgv,
    float* __restrict__ C, int Nb, int ldc,
    const float* __restrict__ resid, const float* __restrict__ pe,
    float* __restrict__ xpe_out)
{
    constexpr int NCH = SPLIT3 ? 96 : 32;
    const char* Ag = (const char*)Agv;
    const char* Bg = (const char*)Bgv;
    extern __shared__ __align__(128) char smem[];
    uint32_t sbase = smem_to_u32(smem);
    const int tid  = threadIdx.x;
    const int wid  = tid >> 5;
    const int lane = tid & 31;
    const int rowBase = blockIdx.y * BM;
    const int colBase = blockIdx.x * BN;
    const int wm = (wid & 3) * 64;
    const int wn = (wid >> 2) * 64;

    float acc[4][8][4];
#pragma unroll
    for (int mi = 0; mi < 4; mi++)
#pragma unroll
        for (int ni = 0; ni < 8; ni++)
#pragma unroll
            for (int e = 0; e < 4; e++) acc[mi][ni][e] = 0.0f;

#pragma unroll
    for (int j = 0; j < STAGES - 1; j++) {
        uint32_t sA = sbase + j * STAGE_BYTES;
        load_chunk<SPLIT3>(sA, sA + A_BYTES, Ag, Bg, rowBase, colBase, Nb, j, tid);
        CP_COMMIT();
    }

    const int aRow = lane & 15;
    const int aCol = (lane >> 4) * 16;
    const int bRow = (lane & 7) + ((lane >> 4) << 3);
    const int bCol = ((lane >> 3) & 1) * 16;

    for (int j = 0; j < NCH; j++) {
        CP_WAIT2();
        __syncthreads();
        if (j + STAGES - 1 < NCH) {
            uint32_t sA2 = sbase + ((j + STAGES - 1) % STAGES) * STAGE_BYTES;
            load_chunk<SPLIT3>(sA2, sA2 + A_BYTES, Ag, Bg, rowBase, colBase, Nb,
                               j + STAGES - 1, tid);
        }
        CP_COMMIT();

        uint32_t sA = sbase + (j % STAGES) * STAGE_BYTES;
        uint32_t sB = sA + A_BYTES;
#pragma unroll
        for (int ks = 0; ks < 2; ks++) {
            uint32_t a[4][4];
#pragma unroll
            for (int mi = 0; mi < 4; mi++)
                ldsm4(a[mi], sA + (wm + mi * 16 + aRow) * ROWB + ks * 32 + aCol);
            uint32_t b[8][2];
#pragma unroll
            for (int nj = 0; nj < 4; nj++) {
                uint32_t r[4];
                ldsm4(r, sB + (wn + nj * 16 + bRow) * ROWB + ks * 32 + bCol);
                b[nj * 2 + 0][0] = r[0]; b[nj * 2 + 0][1] = r[1];
                b[nj * 2 + 1][0] = r[2]; b[nj * 2 + 1][1] = r[3];
            }
#pragma unroll
            for (int mi = 0; mi < 4; mi++)
#pragma unroll
                for (int ni = 0; ni < 8; ni++) {
                    if (SPLIT3) mma_bf16(acc[mi][ni], a[mi], b[ni]);
                    else        mma_fp16(acc[mi][ni], a[mi], b[ni]);
                }
        }
    }

    // epilogue (scalar stores only — ldc may be odd for the LM head)
    const int erow = lane >> 2;
    const int ecol = (lane & 3) * 2;
#pragma unroll
    for (int mi = 0; mi < 4; mi++) {
#pragma unroll
        for (int half = 0; half < 2; half++) {
            int gr = rowBase + wm + mi * 16 + erow + half * 8;
            float* crow = C + (size_t)gr * ldc;
#pragma unroll
            for (int ni = 0; ni < 8; ni++) {
                int gc = colBase + wn + ni * 8 + ecol;
                float v0 = acc[mi][ni][half * 2 + 0];
                float v1 = acc[mi][ni][half * 2 + 1];
                if (MODE == 0) {
                    if (gc < Nb)     crow[gc]     = v0;
                    if (gc + 1 < Nb) crow[gc + 1] = v1;
                } else {
                    const float* rr = resid + (size_t)gr * HID;
                    const float* pp = pe + (size_t)gr * HID;
                    float* xx = xpe_out + (size_t)gr * HID;
                    float w0 = rr[gc] + v0;
                    float w1 = rr[gc + 1] + v1;
                    crow[gc] = w0; crow[gc + 1] = w1;
                    xx[gc] = w0 + pp[gc]; xx[gc + 1] = w1 + pp[gc + 1];
                }
            }
        }
    }
}

// ============================================================
// Flash attention (fp32), causal, hd=64.
// Heavy (large-qt) tiles launch first for better wave packing.
// ============================================================
#define QSCALE (0.125f * 1.44269504088896f)

__global__ __launch_bounds__(256) void attn_kernel(
    const float* __restrict__ qkv, float* __restrict__ out)
{
    __shared__ __align__(16) float Qts[HD][64];
    __shared__ __align__(16) float KP[64][64];
    __shared__ __align__(16) float Vs[64][64];

    int tid = threadIdx.x;
    int tx = tid & 15, ty = tid >> 4;
    int qt = gridDim.x - 1 - blockIdx.x;   // heavy tiles first
    int h  = blockIdx.y;

#pragma unroll
    for (int it = 0; it < 4; it++) {
        int li = tid + it * 256;
        int r  = li >> 4;
        int c4 = (li & 15) * 4;
        float4 v = *reinterpret_cast<const float4*>(
            qkv + (size_t)(qt * 64 + r) * (3 * HID) + h * HD + c4);
        Qts[c4 + 0][r] = v.x * QSCALE; Qts[c4 + 1][r] = v.y * QSCALE;
        Qts[c4 + 2][r] = v.z * QSCALE; Qts[c4 + 3][r] = v.w * QSCALE;
    }

    float m_i[4], l_i[4], o[4][4];
#pragma unroll
    for (int i = 0; i < 4; i++) {
        m_i[i] = -1e30f; l_i[i] = 0.0f;
#pragma unroll
        for (int j = 0; j < 4; j++) o[i][j] = 0.0f;
    }

    for (int kt = 0; kt <= qt; kt++) {
        __syncthreads();
#pragma unroll
        for (int it = 0; it < 4; it++) {
            int li = tid + it * 256;
            int r  = li >> 4;
            int c4 = (li & 15) * 4;
            const float* rowp = qkv + (size_t)(kt * 64 + r) * (3 * HID) + h * HD + c4;
            float4 kv = *reinterpret_cast<const float4*>(rowp + HID);
            KP[c4 + 0][r] = kv.x; KP[c4 + 1][r] = kv.y;
            KP[c4 + 2][r] = kv.z; KP[c4 + 3][r] = kv.w;
            float4 vv = *reinterpret_cast<const float4*>(rowp + 2 * HID);
            *reinterpret_cast<float4*>(&Vs[r][c4]) = vv;
        }
        __syncthreads();

        float s[4][4];
#pragma unroll
        for (int i = 0; i < 4; i++)
#pragma unroll
            for (int j = 0; j < 4; j++) s[i][j] = 0.0f;
#pragma unroll
        for (int kk = 0; kk < HD; kk++) {
            float4 a = *reinterpret_cast<const float4*>(&Qts[kk][ty * 4]);
            float4 b = *reinterpret_cast<const float4*>(&KP[kk][tx * 4]);
            float av[4] = {a.x, a.y, a.z, a.w};
            float bv[4] = {b.x, b.y, b.z, b.w};
#pragma unroll
            for (int i = 0; i < 4; i++)
#pragma unroll
                for (int j = 0; j < 4; j++)
                    s[i][j] = fmaf(av[i], bv[j], s[i][j]);
        }

#pragma unroll
        for (int i = 0; i < 4; i++)
#pragma unroll
            for (int j = 0; j < 4; j++) {
                if (kt == qt && (ty * 4 + i) < (tx * 4 + j)) s[i][j] = -1e30f;
            }

        float p[4][4];
#pragma unroll
        for (int i = 0; i < 4; i++) {
            float rm = fmaxf(fmaxf(s[i][0], s[i][1]), fmaxf(s[i][2], s[i][3]));
            rm = fmaxf(rm, __shfl_xor_sync(0xffffffffu, rm, 1));
            rm = fmaxf(rm, __shfl_xor_sync(0xffffffffu, rm, 2));
            rm = fmaxf(rm, __shfl_xor_sync(0xffffffffu, rm, 4));
            rm = fmaxf(rm, __shfl_xor_sync(0xffffffffu, rm, 8));
            float mn = fmaxf(m_i[i], rm);
            float alpha = exp2f(m_i[i] - mn);
            float rs = 0.0f;
#pragma unroll
            for (int j = 0; j < 4; j++) { p[i][j] = exp2f(s[i][j] - mn); rs += p[i][j]; }
            rs += __shfl_xor_sync(0xffffffffu, rs, 1);
            rs += __shfl_xor_sync(0xffffffffu, rs, 2);
            rs += __shfl_xor_sync(0xffffffffu, rs, 4);
            rs += __shfl_xor_sync(0xffffffffu, rs, 8);
            l_i[i] = l_i[i] * alpha + rs;
            m_i[i] = mn;
#pragma unroll
            for (int j = 0; j < 4; j++) o[i][j] *= alpha;
        }

        __syncthreads();
#pragma unroll
        for (int i = 0; i < 4; i++)
#pragma unroll
            for (int j = 0; j < 4; j++) KP[ty * 4 + i][tx * 4 + j] = p[i][j];
        __syncthreads();

#pragma unroll
        for (int kk = 0; kk < 64; kk++) {
            float a0 = KP[ty * 4 + 0][kk];
            float a1 = KP[ty * 4 + 1][kk];
            float a2 = KP[ty * 4 + 2][kk];
            float a3 = KP[ty * 4 + 3][kk];
            float4 b = *reinterpret_cast<const float4*>(&Vs[kk][tx * 4]);
            float bv[4] = {b.x, b.y, b.z, b.w};
#pragma unroll
            for (int j = 0; j < 4; j++) {
                o[0][j] = fmaf(a0, bv[j], o[0][j]);
                o[1][j] = fmaf(a1, bv[j], o[1][j]);
                o[2][j] = fmaf(a2, bv[j], o[2][j]);
                o[3][j] = fmaf(a3, bv[j], o[3][j]);
            }
        }
    }

#pragma unroll
    for (int i = 0; i < 4; i++) {
        float inv = 1.0f / l_i[i];
        int gq = qt * 64 + ty * 4 + i;
#pragma unroll
        for (int j = 0; j < 4; j++)
            out[(size_t)gq * HID + h * HD + tx * 4 + j] = o[i][j] * inv;
    }
}

// ============================================================
// launch
// ============================================================
extern "C" void kernel_launch(void* const* d_in, const int* in_sizes, int n_in,
                              void* d_out, int out_size)
{
    const int*   ids   = (const int*)d_in[0];
    const float* tok   = (const float*)d_in[1];
    const float* pos   = (const float*)d_in[2];
    const float* Wqkv0 = (const float*)d_in[3];
    const float* Wo0   = (const float*)d_in[4];
    const float* Wqkv1 = (const float*)d_in[5];
    const float* Wo1   = (const float*)d_in[6];
    float* out = (float*)d_out;

    float *x, *xpe, *qkvb, *attnb;
    __nv_bfloat16 *wb, *apb, *axb, *aatb;
    __half *tokh, *axh;
    cudaGetSymbolAddress((void**)&x,     g_x);
    cudaGetSymbolAddress((void**)&xpe,   g_xpe);
    cudaGetSymbolAddress((void**)&qkvb,  g_qkv);
    cudaGetSymbolAddress((void**)&attnb, g_attn);
    cudaGetSymbolAddress((void**)&wb,    g_w);
    cudaGetSymbolAddress((void**)&apb,   g_ap);
    cudaGetSymbolAddress((void**)&axb,   g_ax);
    cudaGetSymbolAddress((void**)&aatb,  g_aat);
    cudaGetSymbolAddress((void**)&tokh,  g_tokh);
    cudaGetSymbolAddress((void**)&axh,   g_axh);

    cudaFuncSetAttribute(mm_kernel<0,1>, cudaFuncAttributeMaxDynamicSharedMemorySize, SMEM_BYTES);
    cudaFuncSetAttribute(mm_kernel<1,1>, cudaFuncAttributeMaxDynamicSharedMemorySize, SMEM_BYTES);
    cudaFuncSetAttribute(mm_kernel<0,0>, cudaFuncAttributeMaxDynamicSharedMemorySize, SMEM_BYTES);

    dim3 blk(256);
    const int SEQ4 = SEQ * 256;
    const int VOC4 = VOCABN * 256;

    // tok_emb fp16 (LM head B)
    conv_half<<<(VOC4 + 255) / 256, blk>>>(tok, tokh, VOC4);

    // embed
    embed_kernel<<<SEQ * HID / 4 / 256, blk>>>(ids, tok, pos);

    dim3 grid_qk(2048 / BN, SEQ / BM);                  // (16, 8)
    dim3 grid_h (1024 / BN, SEQ / BM);                  // (8, 8)
    dim3 grid_lm((VOCABN + BN - 1) / BN, SEQ / BM);     // (393, 8)
    dim3 grid_at(SEQ / 64, NH);

    const float* Wq[2] = {Wqkv0, Wqkv1};
    const float* Wo[2] = {Wo0, Wo1};
    for (int l = 0; l < 2; l++) {
        conv_split<<<SEQ4 / 256, blk>>>(xpe, apb, SEQ4);
        conv_split<<<SEQ4 / 256, blk>>>(x,   axb, SEQ4);
        conv_split<<<(3072 * 256) / 256, blk>>>(Wq[l], wb, 3072 * 256);
        // qk projection: A = xpe', B = Wqkv'[0:2048]
        mm_kernel<0,1><<<grid_qk, blk, SMEM_BYTES>>>(apb, wb, qkvb, 2048, 3 * HID,
                                                     nullptr, nullptr, nullptr);
        // v projection: A = x', B = Wqkv'[2048:3072]
        mm_kernel<0,1><<<grid_h, blk, SMEM_BYTES>>>(axb, wb + (size_t)2048 * KSTOR,
                                                    qkvb + 2048, 1024, 3 * HID,
                                                    nullptr, nullptr, nullptr);
        attn_kernel<<<grid_at, blk>>>(qkvb, attnb);
        conv_split<<<SEQ4 / 256, blk>>>(attnb, aatb, SEQ4);
        conv_split<<<(1024 * 256) / 256, blk>>>(Wo[l], wb, 1024 * 256);
        // out proj + residual + pos-emb fusion
        mm_kernel<1,1><<<grid_h, blk, SMEM_BYTES>>>(aatb, wb, x, 1024, HID, x, pos, xpe);
    }

    // LM head: single-pass fp16, K = 1024
    conv_half<<<SEQ4 / 256, blk>>>(x, axh, SEQ4);
    mm_kernel<0,0><<<grid_lm, blk, SMEM_BYTES>>>(axh, tokh, out, VOCABN, VOCABN,
                                                 nullptr, nullptr, nullptr);
}

// round 15
// speedup vs baseline: 2.8466x; 1.7783x over previous
#include <cuda_runtime.h>
#include <cuda_fp16.h>
#include <cstdint>

#define SEQ 2048
#define HID 1024
#define NH  16
#define HD  64
#define VOCABN 50259

// ---- GEMM config (fp16 single-pass, K = 1024) ----
#define KSB 2048           // bytes per stored row (1024 halfs)
#define NCH 32             // K chunks of 32
#define BM 256
#define BN 128
#define STAGES 4
#define ROWB 80
#define A_BYTES (BM * ROWB)
#define B_BYTES (BN * ROWB)
#define STAGE_BYTES (A_BYTES + B_BYTES)
#define SMEM_BYTES (STAGES * STAGE_BYTES)   // 122880

// ---- attention config ----
#define AQT 128
#define AKT 64
#define AROWB 144          // 64 halfs (128B) + 16B pad
#define ASC (0.125f * 1.44269504088896f)

// ---- scratch ----
__device__ float g_x[SEQ * HID];                              // fp32 residual master
__device__ __align__(16) __half g_xh[SEQ * HID];              // half(x)
__device__ __align__(16) __half g_xpeh[SEQ * HID];            // half(x + pe)
__device__ __align__(16) __half g_qkvh[(size_t)SEQ * 3 * HID];
__device__ __align__(16) __half g_aath[SEQ * HID];            // attn out, half
__device__ __align__(16) __half g_wh[(size_t)3 * HID * HID];  // weight fp16 (reused)
__device__ __align__(16) __half g_tokh[(size_t)VOCABN * HID];

// ============================================================
// helpers
// ============================================================
__device__ __forceinline__ uint32_t smem_to_u32(const void* p) {
    uint32_t a;
    asm("{ .reg .u64 t; cvta.to.shared.u64 t, %1; cvt.u32.u64 %0, t; }" : "=r"(a) : "l"(p));
    return a;
}
__device__ __forceinline__ void cp16(uint32_t dst, const void* src) {
    asm volatile("cp.async.cg.shared.global [%0], [%1], 16;" :: "r"(dst), "l"(src));
}
#define CP_COMMIT() asm volatile("cp.async.commit_group;" ::: "memory")
#define CP_WAIT2()  asm volatile("cp.async.wait_group %0;" :: "n"(STAGES - 2) : "memory")
#define CP_WAIT0()  asm volatile("cp.async.wait_group 0;" ::: "memory")

__device__ __forceinline__ void ldsm4(uint32_t* r, uint32_t addr) {
    asm volatile("ldmatrix.sync.aligned.m8n8.x4.shared.b16 {%0,%1,%2,%3}, [%4];"
                 : "=r"(r[0]), "=r"(r[1]), "=r"(r[2]), "=r"(r[3]) : "r"(addr));
}
__device__ __forceinline__ void ldsm4t(uint32_t* r, uint32_t addr) {
    asm volatile("ldmatrix.sync.aligned.m8n8.x4.trans.shared.b16 {%0,%1,%2,%3}, [%4];"
                 : "=r"(r[0]), "=r"(r[1]), "=r"(r[2]), "=r"(r[3]) : "r"(addr));
}
__device__ __forceinline__ void mma_fp16(float* c, const uint32_t* a, const uint32_t* b) {
    asm volatile(
        "mma.sync.aligned.m16n8k16.row.col.f32.f16.f16.f32 "
        "{%0,%1,%2,%3}, {%4,%5,%6,%7}, {%8,%9}, {%0,%1,%2,%3};"
        : "+f"(c[0]), "+f"(c[1]), "+f"(c[2]), "+f"(c[3])
        : "r"(a[0]), "r"(a[1]), "r"(a[2]), "r"(a[3]), "r"(b[0]), "r"(b[1]));
}
__device__ __forceinline__ uint32_t h2pack(float a, float b) {
    __half2 h = __floats2half2_rn(a, b);
    return *reinterpret_cast<uint32_t*>(&h);
}

// ============================================================
// Embedding: x = tok_emb[ids] (fp32 + half), xpeh = half(x + pos)
// ============================================================
__global__ __launch_bounds__(256) void embed_kernel(
    const int* __restrict__ ids, const float* __restrict__ tok,
    const float* __restrict__ pos)
{
    int i = blockIdx.x * 256 + threadIdx.x;
    int s = i >> 8;
    int c = i & 255;
    int t = ids[s];
    float4 v = reinterpret_cast<const float4*>(tok + (size_t)t * HID)[c];
    float4 p = reinterpret_cast<const float4*>(pos + (size_t)s * HID)[c];
    reinterpret_cast<float4*>(g_x + (size_t)s * HID)[c] = v;
    __half2* xh = reinterpret_cast<__half2*>(g_xh) + i * 2;
    xh[0] = __floats2half2_rn(v.x, v.y);
    xh[1] = __floats2half2_rn(v.z, v.w);
    __half2* xp = reinterpret_cast<__half2*>(g_xpeh) + i * 2;
    xp[0] = __floats2half2_rn(v.x + p.x, v.y + p.y);
    xp[1] = __floats2half2_rn(v.z + p.z, v.w + p.w);
}

// ============================================================
// fp16 conversion (weights / tok_emb): fp32 -> fp16, linear
// ============================================================
__global__ __launch_bounds__(256) void conv_half(
    const float* __restrict__ src, __half* __restrict__ dst, int total4)
{
    int i = blockIdx.x * 256 + threadIdx.x;
    if (i >= total4) return;
    float4 v = reinterpret_cast<const float4*>(src)[i];
    reinterpret_cast<__half2*>(dst)[i * 2 + 0] = __floats2half2_rn(v.x, v.y);
    reinterpret_cast<__half2*>(dst)[i * 2 + 1] = __floats2half2_rn(v.z, v.w);
}

// ============================================================
// fp16 mma GEMM: C[m][n] = sum_k A[m][k] B[n][k]  (K=1024)
// Tile 256x128x32, 8 warps (4Mx2N), 4-stage cp.async.
// MODE 0: C fp32        (LM head; scalar stores, odd ldc OK)
// MODE 1: x = resid+acc (fp32); xh = half(x); xpeh = half(x+pe)
// MODE 2: C fp16        (qkv projections)
// ============================================================
__device__ __forceinline__ void load_chunk(
    uint32_t sA, uint32_t sB, const char* Ag, const char* Bg,
    int rowBase, int colBase, int Nb, int ch, int tid)
{
    const char* abase = Ag + (size_t)ch * 64;
#pragma unroll
    for (int it = 0; it < 4; it++) {
        int q = tid + it * 256;
        int r = q >> 2, cc = q & 3;
        cp16(sA + r * ROWB + cc * 16, abase + (size_t)(rowBase + r) * KSB + cc * 16);
    }
    const char* bbase = Bg + (size_t)ch * 64;
#pragma unroll
    for (int it = 0; it < 2; it++) {
        int q = tid + it * 256;
        int r = q >> 2, cc = q & 3;
        int br = colBase + r;
        if (br > Nb - 1) br = Nb - 1;
        cp16(sB + r * ROWB + cc * 16, bbase + (size_t)br * KSB + cc * 16);
    }
}

template <int MODE>
__global__ __launch_bounds__(256, 1) void mm_kernel(
    const __half* __restrict__ Ag, const __half* __restrict__ Bg,
    void* __restrict__ Cv, int Nb, int ldc,
    const float* __restrict__ pe,
    float* __restrict__ x_out, __half* __restrict__ xh, __half* __restrict__ xpeh)
{
    extern __shared__ __align__(128) char smem[];
    uint32_t sbase = smem_to_u32(smem);
    const int tid  = threadIdx.x;
    const int wid  = tid >> 5;
    const int lane = tid & 31;
    const int rowBase = blockIdx.y * BM;
    const int colBase = blockIdx.x * BN;
    const int wm = (wid & 3) * 64;
    const int wn = (wid >> 2) * 64;

    float acc[4][8][4];
#pragma unroll
    for (int mi = 0; mi < 4; mi++)
#pragma unroll
        for (int ni = 0; ni < 8; ni++)
#pragma unroll
            for (int e = 0; e < 4; e++) acc[mi][ni][e] = 0.0f;

#pragma unroll
    for (int j = 0; j < STAGES - 1; j++) {
        uint32_t sA = sbase + j * STAGE_BYTES;
        load_chunk(sA, sA + A_BYTES, (const char*)Ag, (const char*)Bg,
                   rowBase, colBase, Nb, j, tid);
        CP_COMMIT();
    }

    const int aRow = lane & 15;
    const int aCol = (lane >> 4) * 16;
    const int bRow = (lane & 7) + ((lane >> 4) << 3);
    const int bCol = ((lane >> 3) & 1) * 16;

    for (int j = 0; j < NCH; j++) {
        CP_WAIT2();
        __syncthreads();
        if (j + STAGES - 1 < NCH) {
            uint32_t sA2 = sbase + ((j + STAGES - 1) % STAGES) * STAGE_BYTES;
            load_chunk(sA2, sA2 + A_BYTES, (const char*)Ag, (const char*)Bg,
                       rowBase, colBase, Nb, j + STAGES - 1, tid);
        }
        CP_COMMIT();

        uint32_t sA = sbase + (j % STAGES) * STAGE_BYTES;
        uint32_t sB = sA + A_BYTES;
#pragma unroll
        for (int ks = 0; ks < 2; ks++) {
            uint32_t a[4][4];
#pragma unroll
            for (int mi = 0; mi < 4; mi++)
                ldsm4(a[mi], sA + (wm + mi * 16 + aRow) * ROWB + ks * 32 + aCol);
            uint32_t b[8][2];
#pragma unroll
            for (int nj = 0; nj < 4; nj++) {
                uint32_t r[4];
                ldsm4(r, sB + (wn + nj * 16 + bRow) * ROWB + ks * 32 + bCol);
                b[nj * 2 + 0][0] = r[0]; b[nj * 2 + 0][1] = r[1];
                b[nj * 2 + 1][0] = r[2]; b[nj * 2 + 1][1] = r[3];
            }
#pragma unroll
            for (int mi = 0; mi < 4; mi++)
#pragma unroll
                for (int ni = 0; ni < 8; ni++)
                    mma_fp16(acc[mi][ni], a[mi], b[ni]);
        }
    }

    const int erow = lane >> 2;
    const int ecol = (lane & 3) * 2;
#pragma unroll
    for (int mi = 0; mi < 4; mi++) {
#pragma unroll
        for (int half = 0; half < 2; half++) {
            int gr = rowBase + wm + mi * 16 + erow + half * 8;
#pragma unroll
            for (int ni = 0; ni < 8; ni++) {
                int gc = colBase + wn + ni * 8 + ecol;
                float v0 = acc[mi][ni][half * 2 + 0];
                float v1 = acc[mi][ni][half * 2 + 1];
                if (MODE == 0) {
                    float* crow = (float*)Cv + (size_t)gr * ldc;
                    if (gc < Nb)     crow[gc]     = v0;
                    if (gc + 1 < Nb) crow[gc + 1] = v1;
                } else if (MODE == 2) {
                    __half* crow = (__half*)Cv + (size_t)gr * ldc;
                    *reinterpret_cast<__half2*>(crow + gc) = __floats2half2_rn(v0, v1);
                } else {
                    float* crow = (float*)Cv + (size_t)gr * ldc;   // x fp32
                    const float* pp = pe + (size_t)gr * HID;
                    float w0 = crow[gc] + v0;       // resid (in-place)
                    float w1 = crow[gc + 1] + v1;
                    crow[gc] = w0; crow[gc + 1] = w1;
                    *reinterpret_cast<__half2*>(xh + (size_t)gr * HID + gc) =
                        __floats2half2_rn(w0, w1);
                    *reinterpret_cast<__half2*>(xpeh + (size_t)gr * HID + gc) =
                        __floats2half2_rn(w0 + pp[gc], w1 + pp[gc + 1]);
                }
            }
        }
    }
}

// ============================================================
// fp16 tensor-core flash attention, causal, hd=64.
// Block: 256 thr (8 warps x 16 query rows = 128 queries), kt tiles of 64.
// qkv layout: row s -> [q | k | v] halfs, head h at col h*64.
// ============================================================
__global__ __launch_bounds__(256) void attn_mma(
    const __half* __restrict__ qkv, __half* __restrict__ outh)
{
    __shared__ __align__(16) unsigned char sm[(AQT + 2 * AKT) * AROWB];
    uint32_t sQ = smem_to_u32(sm);
    uint32_t sK = sQ + AQT * AROWB;
    uint32_t sV = sK + AKT * AROWB;

    const int tid = threadIdx.x, wid = tid >> 5, lane = tid & 31;
    const int gid = lane >> 2, tig = lane & 3;
    const int qt = gridDim.x - 1 - blockIdx.x;    // heavy tiles first
    const int h  = blockIdx.y;
    const int qbase = qt * AQT;

    // load Q tile (128 rows x 128 B)
    {
        const __half* qg = qkv + (size_t)qbase * (3 * HID) + h * HD;
#pragma unroll
        for (int it = 0; it < 4; it++) {
            int q = tid + it * 256;
            int r = q >> 3, c = q & 7;
            cp16(sQ + r * AROWB + c * 16, qg + (size_t)r * (3 * HID) + c * 8);
        }
        CP_COMMIT(); CP_WAIT0();
    }
    __syncthreads();

    const int aRow = lane & 15, aCol = (lane >> 4) * 16;
    const int bRow = (lane & 7) + ((lane >> 4) << 3), bCol = ((lane >> 3) & 1) * 16;

    // hoist Q fragments (16 rows x 64 hd per warp)
    uint32_t qa[4][4];
#pragma unroll
    for (int ks = 0; ks < 4; ks++)
        ldsm4(qa[ks], sQ + (wid * 16 + aRow) * AROWB + ks * 32 + aCol);

    float m0 = -1e30f, m1 = -1e30f, l0 = 0.0f, l1 = 0.0f;
    float of[8][4];
#pragma unroll
    for (int j = 0; j < 8; j++)
#pragma unroll
        for (int e = 0; e < 4; e++) of[j][e] = 0.0f;

    const int nkt = 2 * qt + 2;
    for (int kt = 0; kt < nkt; kt++) {
        __syncthreads();   // prior K/V reads done
        {
            const __half* kg = qkv + (size_t)(kt * AKT) * (3 * HID) + HID + h * HD;
            const __half* vg = kg + HID;
#pragma unroll
            for (int it = 0; it < 2; it++) {
                int q = tid + it * 256;
                int r = q >> 3, c = q & 7;
                cp16(sK + r * AROWB + c * 16, kg + (size_t)r * (3 * HID) + c * 8);
                cp16(sV + r * AROWB + c * 16, vg + (size_t)r * (3 * HID) + c * 8);
            }
            CP_COMMIT(); CP_WAIT0();
        }
        __syncthreads();

        // S = Q K^T  (16 x 64 per warp)
        float sf[8][4];
#pragma unroll
        for (int j = 0; j < 8; j++)
#pragma unroll
            for (int e = 0; e < 4; e++) sf[j][e] = 0.0f;
#pragma unroll
        for (int ks = 0; ks < 4; ks++) {
            uint32_t kb[8][2];
#pragma unroll
            for (int n2 = 0; n2 < 4; n2++) {
                uint32_t r[4];
                ldsm4(r, sK + (n2 * 16 + bRow) * AROWB + ks * 32 + bCol);
                kb[n2 * 2 + 0][0] = r[0]; kb[n2 * 2 + 0][1] = r[1];
                kb[n2 * 2 + 1][0] = r[2]; kb[n2 * 2 + 1][1] = r[3];
            }
#pragma unroll
            for (int j = 0; j < 8; j++) mma_fp16(sf[j], qa[ks], kb[j]);
        }

        // causal mask (only tiles overlapping the diagonal)
        if (kt >= 2 * qt) {
            int qr0 = qbase + wid * 16 + gid;
#pragma unroll
            for (int j = 0; j < 8; j++) {
                int kc = kt * AKT + 8 * j + 2 * tig;
#pragma unroll
                for (int e = 0; e < 4; e++) {
                    int kcol = kc + (e & 1);
                    int qr = qr0 + ((e >> 1) << 3);
                    if (qr < kcol) sf[j][e] = -1e30f;
                }
            }
        }

        // online softmax (rows gid and gid+8)
        float mx0 = -1e30f, mx1 = -1e30f;
#pragma unroll
        for (int j = 0; j < 8; j++) {
            mx0 = fmaxf(mx0, fmaxf(sf[j][0], sf[j][1]));
            mx1 = fmaxf(mx1, fmaxf(sf[j][2], sf[j][3]));
        }
        mx0 = fmaxf(mx0, __shfl_xor_sync(0xffffffffu, mx0, 1));
        mx0 = fmaxf(mx0, __shfl_xor_sync(0xffffffffu, mx0, 2));
        mx1 = fmaxf(mx1, __shfl_xor_sync(0xffffffffu, mx1, 1));
        mx1 = fmaxf(mx1, __shfl_xor_sync(0xffffffffu, mx1, 2));
        float mn0 = fmaxf(m0, mx0), mn1 = fmaxf(m1, mx1);
        float al0 = exp2f((m0 - mn0) * ASC);
        float al1 = exp2f((m1 - mn1) * ASC);
        float rs0 = 0.0f, rs1 = 0.0f;
#pragma unroll
        for (int j = 0; j < 8; j++) {
            sf[j][0] = exp2f((sf[j][0] - mn0) * ASC); rs0 += sf[j][0];
            sf[j][1] = exp2f((sf[j][1] - mn0) * ASC); rs0 += sf[j][1];
            sf[j][2] = exp2f((sf[j][2] - mn1) * ASC); rs1 += sf[j][2];
            sf[j][3] = exp2f((sf[j][3] - mn1) * ASC); rs1 += sf[j][3];
        }
        rs0 += __shfl_xor_sync(0xffffffffu, rs0, 1);
        rs0 += __shfl_xor_sync(0xffffffffu, rs0, 2);
        rs1 += __shfl_xor_sync(0xffffffffu, rs1, 1);
        rs1 += __shfl_xor_sync(0xffffffffu, rs1, 2);
        l0 = l0 * al0 + rs0; l1 = l1 * al1 + rs1;
        m0 = mn0; m1 = mn1;
#pragma unroll
        for (int j = 0; j < 8; j++) {
            of[j][0] *= al0; of[j][1] *= al0;
            of[j][2] *= al1; of[j][3] *= al1;
        }

        // pack P as fp16 A-fragments (k-dim = key cols)
        uint32_t pa[4][4];
#pragma unroll
        for (int kk = 0; kk < 4; kk++) {
            pa[kk][0] = h2pack(sf[2 * kk][0],     sf[2 * kk][1]);
            pa[kk][1] = h2pack(sf[2 * kk][2],     sf[2 * kk][3]);
            pa[kk][2] = h2pack(sf[2 * kk + 1][0], sf[2 * kk + 1][1]);
            pa[kk][3] = h2pack(sf[2 * kk + 1][2], sf[2 * kk + 1][3]);
        }

        // O += P V   (V via ldmatrix.trans; B frag rows = keys)
#pragma unroll
        for (int kk = 0; kk < 4; kk++) {
            uint32_t vb[8][2];
#pragma unroll
            for (int n2 = 0; n2 < 4; n2++) {
                uint32_t r[4];
                ldsm4t(r, sV + (16 * kk + (lane & 15)) * AROWB
                          + (16 * n2 + ((lane >> 4) << 3)) * 2);
                vb[n2 * 2 + 0][0] = r[0]; vb[n2 * 2 + 0][1] = r[1];
                vb[n2 * 2 + 1][0] = r[2]; vb[n2 * 2 + 1][1] = r[3];
            }
#pragma unroll
            for (int j = 0; j < 8; j++) mma_fp16(of[j], pa[kk], vb[j]);
        }
    }

    // epilogue: O / l -> half
    float inv0 = 1.0f / l0, inv1 = 1.0f / l1;
    int qr = qbase + wid * 16 + gid;
    __half* o0 = outh + (size_t)qr * HID + h * HD;
    __half* o1 = outh + (size_t)(qr + 8) * HID + h * HD;
#pragma unroll
    for (int j = 0; j < 8; j++) {
        int c = 8 * j + 2 * tig;
        *reinterpret_cast<__half2*>(o0 + c) = __floats2half2_rn(of[j][0] * inv0, of[j][1] * inv0);
        *reinterpret_cast<__half2*>(o1 + c) = __floats2half2_rn(of[j][2] * inv1, of[j][3] * inv1);
    }
}

// ============================================================
// launch
// ============================================================
extern "C" void kernel_launch(void* const* d_in, const int* in_sizes, int n_in,
                              void* d_out, int out_size)
{
    const int*   ids   = (const int*)d_in[0];
    const float* tok   = (const float*)d_in[1];
    const float* pos   = (const float*)d_in[2];
    const float* Wqkv0 = (const float*)d_in[3];
    const float* Wo0   = (const float*)d_in[4];
    const float* Wqkv1 = (const float*)d_in[5];
    const float* Wo1   = (const float*)d_in[6];
    float* out = (float*)d_out;

    float* x;
    __half *xh, *xpeh, *qkvh, *aath, *wh, *tokh;
    cudaGetSymbolAddress((void**)&x,     g_x);
    cudaGetSymbolAddress((void**)&xh,    g_xh);
    cudaGetSymbolAddress((void**)&xpeh,  g_xpeh);
    cudaGetSymbolAddress((void**)&qkvh,  g_qkvh);
    cudaGetSymbolAddress((void**)&aath,  g_aath);
    cudaGetSymbolAddress((void**)&wh,    g_wh);
    cudaGetSymbolAddress((void**)&tokh,  g_tokh);

    cudaFuncSetAttribute(mm_kernel<0>, cudaFuncAttributeMaxDynamicSharedMemorySize, SMEM_BYTES);
    cudaFuncSetAttribute(mm_kernel<1>, cudaFuncAttributeMaxDynamicSharedMemorySize, SMEM_BYTES);
    cudaFuncSetAttribute(mm_kernel<2>, cudaFuncAttributeMaxDynamicSharedMemorySize, SMEM_BYTES);

    dim3 blk(256);
    const int SEQ4 = SEQ * 256;
    const int VOC4 = VOCABN * 256;

    conv_half<<<(VOC4 + 255) / 256, blk>>>(tok, tokh, VOC4);
    embed_kernel<<<SEQ4 / 256, blk>>>(ids, tok, pos);

    dim3 grid_qk(2048 / BN, SEQ / BM);                  // (16, 8)
    dim3 grid_h (1024 / BN, SEQ / BM);                  // (8, 8)
    dim3 grid_lm((VOCABN + BN - 1) / BN, SEQ / BM);     // (393, 8)
    dim3 grid_at(SEQ / AQT, NH);                        // (16, 16)

    const float* Wq[2] = {Wqkv0, Wqkv1};
    const float* Wo[2] = {Wo0, Wo1};
    for (int l = 0; l < 2; l++) {
        conv_half<<<(3 * HID * HID / 4) / 256, blk>>>(Wq[l], wh, 3 * HID * HID / 4);
        // qk projection: A = xpeh, B = Wqkv[0:2048] -> qkvh cols 0..2047 (fp16)
        mm_kernel<2><<<grid_qk, blk, SMEM_BYTES>>>(xpeh, wh, qkvh, 2048, 3 * HID,
                                                   nullptr, nullptr, nullptr, nullptr);
        // v projection: A = xh, B = Wqkv[2048:3072] -> qkvh cols 2048..3071
        mm_kernel<2><<<grid_h, blk, SMEM_BYTES>>>(xh, wh + (size_t)2048 * HID,
                                                  qkvh + 2048, 1024, 3 * HID,
                                                  nullptr, nullptr, nullptr, nullptr);
        attn_mma<<<grid_at, blk>>>(qkvh, aath);
        conv_half<<<(HID * HID / 4) / 256, blk>>>(Wo[l], wh, HID * HID / 4);
        // out proj: x += aath @ Wo^T; xh, xpeh refreshed
        mm_kernel<1><<<grid_h, blk, SMEM_BYTES>>>(aath, wh, x, 1024, HID,
                                                  pos, x, xh, xpeh);
    }

    // LM head: fp32 out
    mm_kernel<0><<<grid_lm, blk, SMEM_BYTES>>>(xh, tokh, out, VOCABN, VOCABN,
                                               nullptr, nullptr, nullptr, nullptr);
}